// round 6
// baseline (speedup 1.0000x reference)
#include <cuda_runtime.h>
#include <cuda_bf16.h>
#include <cstdint>
#include <cstddef>

#define BATCH 512
#define NIN   2048
#define UNITS 4096
#define KTOT  6144
#define OFS   (BATCH*UNITS)

#define BM 128
#define BN 128
#define BK 64                 // K per stage
#define NKS (KTOT/BK)         // 96 stages
#define NKP (NKS/2)           // 48 pairs
#define NSLOT 6               // 3 pairs resident
#define ABYTES 16384u         // 128 rows x 128 B
#define STAGE_BYTES 32768u    // A (16K) + B (16K)
#define GEMM_SMEM (NSLOT*STAGE_BYTES + 1024u)   // 197632

// A tile: 128-B pitch swizzle ; B tile: 256-B pitch swizzle
#define SWZA(x) ((x) ^ (((x) >> 3) & 0x70u))
#define SWZB(x) ((x) ^ (((x) >> 4) & 0x70u))

// reduction scratch layout (reuses stage smem)
#define REDSTRIDE 34          // floats per row (8B-aligned, conflict-free)
#define REDWARP   (64*REDSTRIDE*4)   // 8704 B per warp region

#define NWCB ((KTOT*UNITS/4)/256)
#define NPKB (BATCH*KTOT/512)
#define NDGB (UNITS/256)

#define C_EL      (-70.6f)
#define C_THR     (-50.4f)
#define C_DTGLC   ((float)(30.0/281.0))
#define C_INVCAP  ((float)(1.0/281.0))
#define C_DTTAUW  ((float)(1.0/144.0))
#define C_DTATAUW ((float)(4.0/144.0))
#define C_BW      (0.0805f)
#define C_VRST    (-70.6f)
#define C_CLIP    (281.0f)

__device__ __nv_bfloat16 g_Apack[(size_t)BATCH * KTOT];
__device__ __nv_bfloat16 g_Wbf[(size_t)KTOT * UNITS];
__device__ float g_diag[UNITS];

__device__ __forceinline__ uint32_t smem_u32(const void* p) {
    uint32_t a;
    asm("{ .reg .u64 t; cvta.to.shared.u64 t, %1; cvt.u32.u64 %0, t; }"
        : "=r"(a) : "l"(p));
    return a;
}
__device__ __forceinline__ void cp16(uint32_t saddr, const void* g) {
    asm volatile("cp.async.cg.shared.global [%0], [%1], 16;"
                 :: "r"(saddr), "l"(g));
}
__device__ __forceinline__ void ldmx4(uint32_t& r0, uint32_t& r1,
                                      uint32_t& r2, uint32_t& r3, uint32_t a) {
    asm volatile("ldmatrix.sync.aligned.m8n8.x4.shared.b16 {%0,%1,%2,%3}, [%4];"
                 : "=r"(r0), "=r"(r1), "=r"(r2), "=r"(r3) : "r"(a));
}
__device__ __forceinline__ void ldmx4t(uint32_t& r0, uint32_t& r1,
                                       uint32_t& r2, uint32_t& r3, uint32_t a) {
    asm volatile("ldmatrix.sync.aligned.m8n8.x4.trans.shared.b16 {%0,%1,%2,%3}, [%4];"
                 : "=r"(r0), "=r"(r1), "=r"(r2), "=r"(r3) : "r"(a));
}
__device__ __forceinline__ void mma16816(float& d0, float& d1, float& d2, float& d3,
                                         uint32_t a0, uint32_t a1, uint32_t a2, uint32_t a3,
                                         uint32_t b0, uint32_t b1) {
    asm volatile(
        "mma.sync.aligned.m16n8k16.row.col.f32.bf16.bf16.f32 "
        "{%0,%1,%2,%3}, {%4,%5,%6,%7}, {%8,%9}, {%0,%1,%2,%3};"
        : "+f"(d0), "+f"(d1), "+f"(d2), "+f"(d3)
        : "r"(a0), "r"(a1), "r"(a2), "r"(a3), "r"(b0), "r"(b1));
}

// ---------------- prep: convert W, pack A, extract diag ----------------
__global__ void __launch_bounds__(256)
prep_kernel(const float* __restrict__ inp, const float* __restrict__ z,
            const float* __restrict__ Win, const float* __restrict__ Wrec) {
    int blk = blockIdx.x;
    int tid = threadIdx.x;

    if (blk < NWCB) {
        size_t e = ((size_t)blk * 256 + tid) * 4;
        const float* src = (e < (size_t)NIN * UNITS)
                         ? (Win + e) : (Wrec + (e - (size_t)NIN * UNITS));
        float4 f = *reinterpret_cast<const float4*>(src);
        __nv_bfloat162 p0 = __floats2bfloat162_rn(f.x, f.y);
        __nv_bfloat162 p1 = __floats2bfloat162_rn(f.z, f.w);
        uint2 pk;
        pk.x = *reinterpret_cast<uint32_t*>(&p0);
        pk.y = *reinterpret_cast<uint32_t*>(&p1);
        reinterpret_cast<uint2*>(g_Wbf)[e / 4] = pk;
    } else if (blk < NWCB + NPKB) {
        int idx = (blk - NWCB) * 256 + tid;
        int b = idx / (KTOT / 2);
        int c = idx - b * (KTOT / 2);
        int k = 2 * c;
        float x0, x1;
        if (k < NIN) {
            const float* p = inp + (size_t)b * NIN + k;
            x0 = p[0]; x1 = p[1];
        } else {
            const float* p = z + (size_t)b * UNITS + (k - NIN);
            x0 = p[0]; x1 = p[1];
        }
        reinterpret_cast<__nv_bfloat162*>(g_Apack)[idx] = __floats2bfloat162_rn(x0, x1);
    } else {
        int n = (blk - NWCB - NPKB) * 256 + tid;
        g_diag[n] = __bfloat162float(__float2bfloat16(Wrec[(size_t)n * UNITS + n]));
    }
}

// ---------------- one-stage loader (512 threads) ----------------
__device__ __forceinline__ void load_stage(uint32_t tiles, int tid,
                                           const __nv_bfloat16* Ag,
                                           const __nv_bfloat16* Bg,
                                           int ks, int slot) {
    uint32_t abase = tiles + (uint32_t)slot * STAGE_BYTES;
    uint32_t bbase = abase + ABYTES;
    const __nv_bfloat16* ag = Ag + ks * BK;
    const __nv_bfloat16* bg = Bg + (size_t)(ks * BK) * UNITS;
    #pragma unroll
    for (int i = 0; i < 2; i++) {           // A: 128 rows x 8 chunks
        int id = tid + i * 512;
        int row = id >> 3, cg = id & 7;
        uint32_t off = SWZA((uint32_t)(row * 128 + cg * 16));
        cp16(abase + off, ag + (size_t)row * KTOT + cg * 8);
    }
    #pragma unroll
    for (int i = 0; i < 2; i++) {           // B: 64 k-rows x 16 chunks
        int id = tid + i * 512;
        int row = id >> 4, cg = id & 15;
        uint32_t off = SWZB((uint32_t)(row * 256 + cg * 16));
        cp16(bbase + off, bg + (size_t)row * UNITS + cg * 8);
    }
}

// ---------------- AdEx elementwise ----------------
__device__ __forceinline__ void adex_one(float it, float vo, float wo, float zo,
                                         int ro, float& nv, float& nz,
                                         float& nw, float& nr) {
    float ex = expf((vo - C_THR) * 0.5f);
    ex = fminf(ex, C_CLIP);
    float nv0 = vo - C_DTGLC * (vo - C_EL) + (2.0f * C_DTGLC) * ex
              + (it - wo) * C_INVCAP;
    nv = (zo > 0.5f) ? C_VRST : nv0;
    nw = wo - wo * C_DTTAUW + C_DTATAUW * (vo - C_EL) + C_BW * zo;
    bool sp = (nv > C_THR) && (ro <= 0);
    nz = sp ? 1.0f : 0.0f;
    int nri = ro - 1 + (sp ? 2 : 0);
    nri = nri < 0 ? 0 : (nri > 2 ? 2 : nri);
    nr = (float)nri;
}

// ---------------- GEMM (split-K in CTA) + AdEx epilogue ----------------
__global__ void __launch_bounds__(512, 1)
adex_gemm_kernel(const float* __restrict__ v_in, const int* __restrict__ r_in,
                 const float* __restrict__ w_in, const float* __restrict__ z_in,
                 float* __restrict__ out) {
    extern __shared__ char smem[];
    uint32_t tiles = (smem_u32(smem) + 1023u) & ~1023u;
    int tid = threadIdx.x;
    int wid = tid >> 5;
    int lane = tid & 31;
    int group = wid >> 3;       // 0 / 1 : K-split halves
    int gw = wid & 7;           // warp index within group

    int m0 = (blockIdx.x & 3) * BM;
    int n0 = (blockIdx.x >> 2) * BN;
    int wm = (gw & 1) * 64;     // 2 warps in M
    int wn = (gw >> 1) * 32;    // 4 warps in N

    const __nv_bfloat16* Ag = g_Apack + (size_t)m0 * KTOT;
    const __nv_bfloat16* Bg = g_Wbf + n0;

    float acc[4][4][4];
    #pragma unroll
    for (int i = 0; i < 4; i++)
        #pragma unroll
        for (int j = 0; j < 4; j++)
            #pragma unroll
            for (int q = 0; q < 4; q++) acc[i][j][q] = 0.0f;

    // prologue: pairs 0 and 1 (stages 0..3), one commit group per pair
    load_stage(tiles, tid, Ag, Bg, 0, 0);
    load_stage(tiles, tid, Ag, Bg, 1, 1);
    asm volatile("cp.async.commit_group;");
    load_stage(tiles, tid, Ag, Bg, 2, 2);
    load_stage(tiles, tid, Ag, Bg, 3, 3);
    asm volatile("cp.async.commit_group;");

    int lrow = lane & 15;
    int lcg  = (lane >> 4) * 16;

    uint32_t aoff[4];
    #pragma unroll
    for (int mf = 0; mf < 4; ++mf)
        aoff[mf] = (uint32_t)((wm + mf * 16 + lrow) * 128 + lcg);
    uint32_t boff[2];
    #pragma unroll
    for (int p = 0; p < 2; ++p)
        boff[p] = (uint32_t)(lrow * 256 + wn * 2 + p * 32 + lcg);

    for (int p = 0; p < NKP; ++p) {
        asm volatile("cp.async.wait_group %0;" :: "n"(1));
        __syncthreads();

        // prefetch pair p+2 (into slots of pair p-1, already consumed)
        int kf = 2 * (p + 2);
        if (kf < NKS) {
            load_stage(tiles, tid, Ag, Bg, kf,     kf % NSLOT);
            load_stage(tiles, tid, Ag, Bg, kf + 1, (kf + 1) % NSLOT);
        }
        asm volatile("cp.async.commit_group;");

        // compute my stage of this pair
        int ks = 2 * p + group;
        uint32_t abase = tiles + (uint32_t)(ks % NSLOT) * STAGE_BYTES;
        uint32_t bbase = abase + ABYTES;

        #pragma unroll
        for (int kk = 0; kk < BK / 16; ++kk) {     // 4 k-steps
            uint32_t af[4][4], bfr[4][2];
            uint32_t kba = (uint32_t)(kk * 32);    // A: +32 B in k
            uint32_t kbb = (uint32_t)(kk * 4096);  // B: +16 k-rows
            #pragma unroll
            for (int mf = 0; mf < 4; ++mf)
                ldmx4(af[mf][0], af[mf][1], af[mf][2], af[mf][3],
                      abase + SWZA(aoff[mf] + kba));
            #pragma unroll
            for (int pp = 0; pp < 2; ++pp) {
                uint32_t r0, r1, r2, r3;
                ldmx4t(r0, r1, r2, r3, bbase + SWZB(boff[pp] + kbb));
                bfr[pp * 2 + 0][0] = r0; bfr[pp * 2 + 0][1] = r1;
                bfr[pp * 2 + 1][0] = r2; bfr[pp * 2 + 1][1] = r3;
            }
            #pragma unroll
            for (int mf = 0; mf < 4; ++mf)
                #pragma unroll
                for (int nf = 0; nf < 4; ++nf)
                    mma16816(acc[mf][nf][0], acc[mf][nf][1],
                             acc[mf][nf][2], acc[mf][nf][3],
                             af[mf][0], af[mf][1], af[mf][2], af[mf][3],
                             bfr[nf][0], bfr[nf][1]);
        }
    }

    // ---------------- reduce group1 into group0 via smem ----------------
    asm volatile("cp.async.wait_group %0;" :: "n"(0));
    __syncthreads();    // all compute done; stage smem reusable

    int gid = lane >> 2;
    int qn  = (lane & 3) * 2;
    uint32_t redbase = tiles + (uint32_t)gw * REDWARP;

    if (group == 1) {
        #pragma unroll
        for (int mf = 0; mf < 4; ++mf)
            #pragma unroll
            for (int g = 0; g < 2; ++g) {
                int rloc = mf * 16 + g * 8 + gid;
                #pragma unroll
                for (int nf = 0; nf < 4; ++nf) {
                    uint32_t addr = redbase +
                        (uint32_t)((rloc * REDSTRIDE + nf * 8 + qn) * 4);
                    asm volatile("st.shared.v2.f32 [%0], {%1, %2};"
                                 :: "r"(addr), "f"(acc[mf][nf][g * 2 + 0]),
                                    "f"(acc[mf][nf][g * 2 + 1]) : "memory");
                }
            }
    }
    __syncthreads();

    if (group == 0) {
        #pragma unroll
        for (int mf = 0; mf < 4; ++mf)
            #pragma unroll
            for (int g = 0; g < 2; ++g) {
                int rloc = mf * 16 + g * 8 + gid;
                #pragma unroll
                for (int nf = 0; nf < 4; ++nf) {
                    uint32_t addr = redbase +
                        (uint32_t)((rloc * REDSTRIDE + nf * 8 + qn) * 4);
                    float t0, t1;
                    asm volatile("ld.shared.v2.f32 {%0, %1}, [%2];"
                                 : "=f"(t0), "=f"(t1) : "r"(addr));
                    acc[mf][nf][g * 2 + 0] += t0;
                    acc[mf][nf][g * 2 + 1] += t1;
                }
            }

        // ------------- epilogue (group 0 only) -------------
        #pragma unroll
        for (int mf = 0; mf < 4; ++mf) {
            #pragma unroll
            for (int g = 0; g < 2; ++g) {
                int b = m0 + wm + mf * 16 + g * 8 + gid;
                size_t rowbase = (size_t)b * UNITS + n0 + wn;
                #pragma unroll
                for (int nf = 0; nf < 4; ++nf) {
                    size_t ofs = rowbase + nf * 8 + qn;
                    int ncol = n0 + wn + nf * 8 + qn;
                    float2 vv = *reinterpret_cast<const float2*>(v_in + ofs);
                    float2 ww = *reinterpret_cast<const float2*>(w_in + ofs);
                    float2 zz = *reinterpret_cast<const float2*>(z_in + ofs);
                    int2   rr = *reinterpret_cast<const int2*>(r_in + ofs);
                    float2 dg = *reinterpret_cast<const float2*>(g_diag + ncol);
                    float i0 = acc[mf][nf][g * 2 + 0] - zz.x * dg.x;
                    float i1 = acc[mf][nf][g * 2 + 1] - zz.y * dg.y;
                    float2 ov, oz, ow, orr;
                    adex_one(i0, vv.x, ww.x, zz.x, rr.x, ov.x, oz.x, ow.x, orr.x);
                    adex_one(i1, vv.y, ww.y, zz.y, rr.y, ov.y, oz.y, ow.y, orr.y);
                    *reinterpret_cast<float2*>(out + 0 * (size_t)OFS + ofs) = ov;
                    *reinterpret_cast<float2*>(out + 1 * (size_t)OFS + ofs) = oz;
                    *reinterpret_cast<float2*>(out + 2 * (size_t)OFS + ofs) = ow;
                    *reinterpret_cast<float2*>(out + 3 * (size_t)OFS + ofs) = orr;
                }
            }
        }
    }
}

// ---------------- launch ----------------
extern "C" void kernel_launch(void* const* d_in, const int* in_sizes, int n_in,
                              void* d_out, int out_size) {
    const float* inputs = (const float*)d_in[0];
    const float* v      = (const float*)d_in[1];
    const int*   r      = (const int*)d_in[2];
    const float* w      = (const float*)d_in[3];
    const float* z      = (const float*)d_in[4];
    const float* Win    = (const float*)d_in[5];
    const float* Wrec   = (const float*)d_in[6];
    float* out = (float*)d_out;
    (void)in_sizes; (void)n_in; (void)out_size;

    cudaFuncSetAttribute(adex_gemm_kernel,
                         cudaFuncAttributeMaxDynamicSharedMemorySize, GEMM_SMEM);

    prep_kernel<<<NWCB + NPKB + NDGB, 256>>>(inputs, z, Win, Wrec);
    adex_gemm_kernel<<<128, 512, GEMM_SMEM>>>(v, r, w, z, out);
}